// round 1
// baseline (speedup 1.0000x reference)
#include <cuda_runtime.h>
#include <cuda_bf16.h>

#define N_NODES_MAX 100000
#define LATDIM 128
#define VEC 32   // LATDIM / 4 float4 per row

// Ping-pong scratch buffers (allocation-free rule: __device__ globals)
__device__ float g_bufA[(size_t)N_NODES_MAX * LATDIM];
__device__ float g_bufB[(size_t)N_NODES_MAX * LATDIM];

// ---------------------------------------------------------------------------
// LayerNorm: one warp per node, lane owns one float4 (4 of 128 elems)
// ---------------------------------------------------------------------------
__global__ void ln_kernel(const float* __restrict__ in, float* __restrict__ out,
                          int n_nodes) {
    int gw   = (blockIdx.x * blockDim.x + threadIdx.x) >> 5;
    int lane = threadIdx.x & 31;
    if (gw >= n_nodes) return;

    const float4* in4 = reinterpret_cast<const float4*>(in) + (size_t)gw * VEC;
    float4 v = in4[lane];

    float s  = v.x + v.y + v.z + v.w;
    float ss = v.x * v.x + v.y * v.y + v.z * v.z + v.w * v.w;
    #pragma unroll
    for (int o = 16; o > 0; o >>= 1) {
        s  += __shfl_xor_sync(0xFFFFFFFFu, s,  o);
        ss += __shfl_xor_sync(0xFFFFFFFFu, ss, o);
    }
    float mu  = s * (1.0f / LATDIM);
    float var = ss * (1.0f / LATDIM) - mu * mu;
    float inv = rsqrtf(var + 1e-5f);

    v.x = (v.x - mu) * inv;
    v.y = (v.y - mu) * inv;
    v.z = (v.z - mu) * inv;
    v.w = (v.w - mu) * inv;

    float4* out4 = reinterpret_cast<float4*>(out) + (size_t)gw * VEC;
    out4[lane] = v;
}

// ---------------------------------------------------------------------------
// Zero-fill (grid-stride, float4)
// ---------------------------------------------------------------------------
__global__ void zero_kernel(float4* __restrict__ p, size_t n4) {
    size_t i      = (size_t)blockIdx.x * blockDim.x + threadIdx.x;
    size_t stride = (size_t)gridDim.x * blockDim.x;
    float4 z = make_float4(0.f, 0.f, 0.f, 0.f);
    for (; i < n4; i += stride) p[i] = z;
}

// ---------------------------------------------------------------------------
// SpMM (COO): warp per edge. Lane l handles float4 #l of the 128-dim row.
// y[row] += val * x[col]   via float4 atomicAdd (RED.V4 on sm_90+)
// ---------------------------------------------------------------------------
__global__ void spmm_kernel(const int* __restrict__ row,
                            const int* __restrict__ col,
                            const float* __restrict__ val,
                            const float* __restrict__ x,
                            float* __restrict__ y,
                            int n_edges) {
    int e = (blockIdx.x * blockDim.x + threadIdx.x) >> 5;
    if (e >= n_edges) return;
    int lane = threadIdx.x & 31;

    int   r = __ldg(row + e);
    int   c = __ldg(col + e);
    float v = __ldg(val + e);

    float4 xv = __ldg(reinterpret_cast<const float4*>(x) + (size_t)c * VEC + lane);
    float4 m  = make_float4(v * xv.x, v * xv.y, v * xv.z, v * xv.w);

    atomicAdd(reinterpret_cast<float4*>(y) + (size_t)r * VEC + lane, m);
}

// ---------------------------------------------------------------------------
// acc += src (grid-stride, float4)
// ---------------------------------------------------------------------------
__global__ void acc_add_kernel(float4* __restrict__ acc,
                               const float4* __restrict__ src, size_t n4) {
    size_t i      = (size_t)blockIdx.x * blockDim.x + threadIdx.x;
    size_t stride = (size_t)gridDim.x * blockDim.x;
    for (; i < n4; i += stride) {
        float4 a = acc[i];
        float4 b = src[i];
        a.x += b.x; a.y += b.y; a.z += b.z; a.w += b.w;
        acc[i] = a;
    }
}

// ---------------------------------------------------------------------------
// Launcher
// ---------------------------------------------------------------------------
extern "C" void kernel_launch(void* const* d_in, const int* in_sizes, int n_in,
                              void* d_out, int out_size) {
    const float* embeds  = (const float*)d_in[0];
    const int*   adj_row = (const int*)d_in[1];
    const int*   adj_col = (const int*)d_in[2];
    const float* adj_val = (const float*)d_in[3];

    int n_nodes = in_sizes[0] / LATDIM;
    int n_edges = in_sizes[1];

    float* bufA = nullptr;
    float* bufB = nullptr;
    cudaGetSymbolAddress((void**)&bufA, g_bufA);
    cudaGetSymbolAddress((void**)&bufB, g_bufB);

    float* out = (float*)d_out;
    size_t n4  = (size_t)n_nodes * VEC;   // float4 count

    const int TPB = 256;

    // d_out is poisoned; zero it (it's the accumulator)
    {
        int blocks = 2048;
        zero_kernel<<<blocks, TPB>>>(reinterpret_cast<float4*>(out), n4);
    }

    // LayerNorm: embeds -> bufA
    {
        int warps_needed = n_nodes;
        int blocks = (warps_needed * 32 + TPB - 1) / TPB;
        ln_kernel<<<blocks, TPB>>>(embeds, bufA, n_nodes);
    }

    // 3 layers, ping-pong A <-> B
    float* x = bufA;
    float* y = bufB;
    int spmm_blocks = ((size_t)n_edges * 32 + TPB - 1) / TPB;
    for (int l = 0; l < 3; ++l) {
        zero_kernel<<<2048, TPB>>>(reinterpret_cast<float4*>(y), n4);
        spmm_kernel<<<spmm_blocks, TPB>>>(adj_row, adj_col, adj_val, x, y, n_edges);
        acc_add_kernel<<<2048, TPB>>>(reinterpret_cast<float4*>(out),
                                      reinterpret_cast<const float4*>(y), n4);
        float* t = x; x = y; y = t;
    }
}

// round 2
// speedup vs baseline: 1.4974x; 1.4974x over previous
#include <cuda_runtime.h>
#include <cuda_bf16.h>

#define NMAX   100000
#define EMAX   640000
#define LATDIM 128
#define VEC    32          // float4 per row
#define SCAN_B 1024        // scan block width

// ---- scratch (allocation-free rule: __device__ globals) --------------------
__device__ float g_bufA[(size_t)NMAX * LATDIM];
__device__ float g_bufB[(size_t)NMAX * LATDIM];
__device__ int   g_cnt[NMAX];        // per-row degree
__device__ int   g_ofs[NMAX];        // scatter cursors
__device__ int   g_rowstart[NMAX];   // per-block-local exclusive scan
__device__ int   g_bsum[SCAN_B];     // per-scan-block totals
__device__ int   g_bpref[SCAN_B];    // exclusive scan of totals
__device__ uint2 g_edges[EMAX];      // sorted-by-row {col, val bits}

// ---------------------------------------------------------------------------
// LayerNorm: warp per node, lane owns one float4
// ---------------------------------------------------------------------------
__global__ void ln_kernel(const float* __restrict__ in, float* __restrict__ out,
                          int n_nodes) {
    int gw   = (blockIdx.x * blockDim.x + threadIdx.x) >> 5;
    int lane = threadIdx.x & 31;
    if (gw >= n_nodes) return;

    float4 v = reinterpret_cast<const float4*>(in)[(size_t)gw * VEC + lane];

    float s  = v.x + v.y + v.z + v.w;
    float ss = v.x * v.x + v.y * v.y + v.z * v.z + v.w * v.w;
    #pragma unroll
    for (int o = 16; o > 0; o >>= 1) {
        s  += __shfl_xor_sync(0xFFFFFFFFu, s,  o);
        ss += __shfl_xor_sync(0xFFFFFFFFu, ss, o);
    }
    float mu  = s * (1.0f / LATDIM);
    float var = ss * (1.0f / LATDIM) - mu * mu;
    float inv = rsqrtf(var + 1e-5f);

    v.x = (v.x - mu) * inv; v.y = (v.y - mu) * inv;
    v.z = (v.z - mu) * inv; v.w = (v.w - mu) * inv;

    reinterpret_cast<float4*>(out)[(size_t)gw * VEC + lane] = v;
}

// ---------------------------------------------------------------------------
// CSR build: zero counters -> histogram -> 2-level scan -> scatter
// ---------------------------------------------------------------------------
__global__ void zero_counts_kernel(int n_nodes) {
    int i = blockIdx.x * blockDim.x + threadIdx.x;
    if (i < n_nodes) { g_cnt[i] = 0; g_ofs[i] = 0; }
}

__global__ void hist_kernel(const int* __restrict__ row, int n_edges) {
    int e      = blockIdx.x * blockDim.x + threadIdx.x;
    int stride = gridDim.x * blockDim.x;
    for (; e < n_edges; e += stride) atomicAdd(&g_cnt[row[e]], 1);
}

// block-local exclusive scan over 1024 counts; emit block totals
__global__ void scan1_kernel(int n_nodes) {
    __shared__ int s[SCAN_B];
    int t = threadIdx.x;
    int i = blockIdx.x * SCAN_B + t;
    int v = (i < n_nodes) ? g_cnt[i] : 0;
    s[t] = v;
    __syncthreads();
    #pragma unroll
    for (int off = 1; off < SCAN_B; off <<= 1) {
        int add = (t >= off) ? s[t - off] : 0;
        __syncthreads();
        s[t] += add;
        __syncthreads();
    }
    if (i < n_nodes) g_rowstart[i] = s[t] - v;          // exclusive
    if (t == SCAN_B - 1) g_bsum[blockIdx.x] = s[t];     // block total
}

// single-block exclusive scan of the block totals
__global__ void scan2_kernel(int n_blocks) {
    __shared__ int s[SCAN_B];
    int t = threadIdx.x;
    int v = (t < n_blocks) ? g_bsum[t] : 0;
    s[t] = v;
    __syncthreads();
    #pragma unroll
    for (int off = 1; off < SCAN_B; off <<= 1) {
        int add = (t >= off) ? s[t - off] : 0;
        __syncthreads();
        s[t] += add;
        __syncthreads();
    }
    g_bpref[t] = s[t] - v;
}

__global__ void scatter_kernel(const int* __restrict__ row,
                               const int* __restrict__ col,
                               const float* __restrict__ val,
                               int n_edges) {
    int e      = blockIdx.x * blockDim.x + threadIdx.x;
    int stride = gridDim.x * blockDim.x;
    for (; e < n_edges; e += stride) {
        int r    = row[e];
        int base = g_rowstart[r] + g_bpref[r >> 10];
        int k    = atomicAdd(&g_ofs[r], 1);
        g_edges[base + k] = make_uint2((unsigned)col[e], __float_as_uint(val[e]));
    }
}

// ---------------------------------------------------------------------------
// SpMM: warp per row, register accumulation, NO atomics.
// MODE 0: y = acc; out  = acc      (layer 1; out needs no pre-zero)
// MODE 1: y = acc; out += acc      (layer 2)
// MODE 2:          out += acc      (layer 3; no y store)
// ---------------------------------------------------------------------------
template <int MODE>
__global__ void spmm_row_kernel(const float* __restrict__ x,
                                float* __restrict__ y,
                                float* __restrict__ out,
                                int n_nodes) {
    int r = (blockIdx.x * blockDim.x + threadIdx.x) >> 5;
    if (r >= n_nodes) return;
    int lane = threadIdx.x & 31;

    int base = g_rowstart[r] + g_bpref[r >> 10];
    int deg  = g_cnt[r];

    const float4* x4 = reinterpret_cast<const float4*>(x);
    float4 acc = make_float4(0.f, 0.f, 0.f, 0.f);

    for (int s = 0; s < deg; s += 32) {
        int m = deg - s; if (m > 32) m = 32;
        uint2 ev = make_uint2(0u, 0u);
        if (lane < m) ev = g_edges[base + s + lane];   // coalesced edge-meta load
        #pragma unroll 4
        for (int k = 0; k < m; ++k) {
            int   c = __shfl_sync(0xFFFFFFFFu, (int)ev.x, k);
            float v = __uint_as_float(__shfl_sync(0xFFFFFFFFu, (int)ev.y, k));
            float4 xv = __ldg(x4 + (size_t)c * VEC + lane);
            acc.x += v * xv.x; acc.y += v * xv.y;
            acc.z += v * xv.z; acc.w += v * xv.w;
        }
    }

    size_t oidx = (size_t)r * VEC + lane;
    if (MODE == 0) {
        reinterpret_cast<float4*>(y)[oidx]   = acc;
        reinterpret_cast<float4*>(out)[oidx] = acc;
    } else if (MODE == 1) {
        reinterpret_cast<float4*>(y)[oidx] = acc;
        float4 o = reinterpret_cast<float4*>(out)[oidx];
        o.x += acc.x; o.y += acc.y; o.z += acc.z; o.w += acc.w;
        reinterpret_cast<float4*>(out)[oidx] = o;
    } else {
        float4 o = reinterpret_cast<float4*>(out)[oidx];
        o.x += acc.x; o.y += acc.y; o.z += acc.z; o.w += acc.w;
        reinterpret_cast<float4*>(out)[oidx] = o;
    }
}

// ---------------------------------------------------------------------------
// Launcher
// ---------------------------------------------------------------------------
extern "C" void kernel_launch(void* const* d_in, const int* in_sizes, int n_in,
                              void* d_out, int out_size) {
    const float* embeds  = (const float*)d_in[0];
    const int*   adj_row = (const int*)d_in[1];
    const int*   adj_col = (const int*)d_in[2];
    const float* adj_val = (const float*)d_in[3];

    int n_nodes = in_sizes[0] / LATDIM;
    int n_edges = in_sizes[1];

    float* bufA = nullptr;
    float* bufB = nullptr;
    cudaGetSymbolAddress((void**)&bufA, g_bufA);
    cudaGetSymbolAddress((void**)&bufB, g_bufB);
    float* out = (float*)d_out;

    const int TPB = 256;
    int node_warp_blocks = (n_nodes * 32 + TPB - 1) / TPB;
    int scan_blocks      = (n_nodes + SCAN_B - 1) / SCAN_B;

    // LayerNorm: embeds -> bufA
    ln_kernel<<<node_warp_blocks, TPB>>>(embeds, bufA, n_nodes);

    // CSR build (once, reused by all 3 layers)
    zero_counts_kernel<<<(n_nodes + TPB - 1) / TPB, TPB>>>(n_nodes);
    hist_kernel<<<1024, TPB>>>(adj_row, n_edges);
    scan1_kernel<<<scan_blocks, SCAN_B>>>(n_nodes);
    scan2_kernel<<<1, SCAN_B>>>(scan_blocks);
    scatter_kernel<<<1024, TPB>>>(adj_row, adj_col, adj_val, n_edges);

    // 3 GNN layers, fused accumulation into out
    spmm_row_kernel<0><<<node_warp_blocks, TPB>>>(bufA, bufB, out, n_nodes);
    spmm_row_kernel<1><<<node_warp_blocks, TPB>>>(bufB, bufA, out, n_nodes);
    spmm_row_kernel<2><<<node_warp_blocks, TPB>>>(bufA, nullptr, out, n_nodes);
}